// round 15
// baseline (speedup 1.0000x reference)
#include <cuda_runtime.h>
#include <cuda_fp16.h>
#include <cstdint>

// HMMA (mma.sync) reformulation of the PUMA crossbar MVM conv.
// Exactness chain (validated R1-R13):  S = sum_l xi16*dw,
//   out = clip(RNE(S/4096))/4096,  xi16 = sext16(rint(x*4096)), dw = rint(w*4096).
// fp16-exact split: xi16 = (xi & ~2047) + (xi & 2047); both parts and dw
// (<2048) are exact fp16. K folded: A=[hi;lo] (K=1152), B=[w;w].
// Products exact; fp32 tensor accumulation can flip ~1% of outputs by one
// 1/4096 LSB -> rel_err ~3e-5 << 1e-3. Deterministic (fixed order).
//
// No sm_103a-gated instructions: mma.sync/ldmatrix/cp.async are baseline PTX.

namespace {
constexpr int CIN = 64, H = 16, W = 16, COUT = 128;
constexpr int L = 576, K2 = 1152, P = 1024;
constexpr int NCHUNK = 18;            // K chunks of 64
constexpr int THREADS = 256;          // 8 warps, warp tile m16 x n16
// SMEM: A[2][16 rows][8 units], B[2][128 n][8 units], unit = 16B (8 halves)
constexpr int SA_BYTES = 2048, SB_BYTES = 16384;
constexpr int OFF_B = 4096;           // [A0][A1][B0][B1]
}

__device__ __align__(16) __half A_g[P * K2];     // [pt][c][u][r] x 8 halves
__device__ __align__(16) __half B_g[COUT * K2];  // [c][u][n] x 8 halves

__device__ __forceinline__ uint32_t smem_u32(const void* p) {
    uint32_t a;
    asm("{ .reg .u64 t; cvta.to.shared.u64 t, %1; cvt.u32.u64 %0, t; }"
        : "=r"(a) : "l"(p));
    return a;
}

#define CP_ASYNC16(dst, src) \
    asm volatile("cp.async.cg.shared.global [%0], [%1], 16;" \
                 :: "r"(dst), "l"(src) : "memory")
#define CP_COMMIT() asm volatile("cp.async.commit_group;" ::: "memory")
#define CP_WAIT1()  asm volatile("cp.async.wait_group 1;" ::: "memory")
#define CP_WAIT0()  asm volatile("cp.async.wait_group 0;" ::: "memory")

__device__ __forceinline__ void ldsm4(uint32_t& r0, uint32_t& r1,
                                      uint32_t& r2, uint32_t& r3, uint32_t a) {
    asm volatile("ldmatrix.sync.aligned.m8n8.x4.shared.b16 {%0,%1,%2,%3}, [%4];"
                 : "=r"(r0), "=r"(r1), "=r"(r2), "=r"(r3) : "r"(a));
}
__device__ __forceinline__ void mma16816(float* d, uint32_t a0, uint32_t a1,
                                         uint32_t a2, uint32_t a3,
                                         uint32_t b0, uint32_t b1) {
    asm volatile(
        "mma.sync.aligned.m16n8k16.row.col.f32.f16.f16.f32 "
        "{%0,%1,%2,%3}, {%4,%5,%6,%7}, {%8,%9}, {%0,%1,%2,%3};"
        : "+f"(d[0]), "+f"(d[1]), "+f"(d[2]), "+f"(d[3])
        : "r"(a0), "r"(a1), "r"(a2), "r"(a3), "r"(b0), "r"(b1));
}

// ---- prep: quantize, fp16-split, im2col into the exact staging layout ----
__global__ void prep_kernel(const float* __restrict__ x,
                            const float* __restrict__ w)
{
    int i = blockIdx.x * blockDim.x + threadIdx.x;
    if (i < COUT * L) {
        int n = i / L, l = i - n * L;
        __half h = __float2half_rn(rintf(w[i] * 4096.0f));   // |dw|<2048 exact
        #pragma unroll
        for (int d = 0; d < 2; ++d) {
            int k = l + d * L;
            int c = k >> 6, u = (k >> 3) & 7, hh = k & 7;
            B_g[((c * 8 + u) * COUT + n) * 8 + hh] = h;
        }
    }
    if (i < P * L) {
        int p = i / L, l = i - p * L;
        int b = p >> 8, oh = (p >> 4) & 15, ow = p & 15;
        int ci = l / 9, r9 = l - ci * 9, ki = r9 / 3, kj = r9 - ki * 3;
        int row = oh - 1 + ki, col = ow - 1 + kj;
        int xi = 0;
        if ((unsigned)row < 16u && (unsigned)col < 16u)
            xi = (int)rintf(x[((b * CIN + ci) * H + row) * W + col] * 4096.0f);
        xi = (xi << 16) >> 16;                     // 16-bit two's complement
        int hi = xi & ~2047, lo = xi & 2047;       // exact fp16 split
        int pt = p >> 4, r = p & 15;
        int vals[2] = {hi, lo};
        #pragma unroll
        for (int d = 0; d < 2; ++d) {
            int k = l + d * L;
            int c = k >> 6, u = (k >> 3) & 7, hh = k & 7;
            A_g[(((pt * NCHUNK + c) * 8 + u) * 16 + r) * 8 + hh] =
                __float2half_rn((float)vals[d]);
        }
    }
}

// ---- GEMM: 64 blocks (one per (b,oh)), 8 warps, M=16 N=128 K=1152 ----
__global__ __launch_bounds__(THREADS, 1)
void gemm_kernel(float* __restrict__ out)
{
    __shared__ __align__(16) char smem[OFF_B + 2 * SB_BYTES];   // 36864 B
    const uint32_t sb = smem_u32(smem);
    const int tid = threadIdx.x, wid = tid >> 5, lid = tid & 31;
    const int pt = blockIdx.x;
    const int wn = wid * 16;

    const char* Ag = (const char*)A_g;
    const char* Bg = (const char*)B_g;

    // precomputed lane offsets for ldmatrix (matrix id m = lid>>3)
    const uint32_t aoff = (uint32_t)((lid >> 4) * 256                 // k-unit half
                        + (((lid >> 3) & 1) * 8 + (lid & 7)) * 16);   // row
    const uint32_t boff = (uint32_t)(((lid >> 3) & 1) * 2048          // k-unit half
                        + (wn + ((lid >> 4) * 8) + (lid & 7)) * 16);  // n row

    float d0[4] = {0, 0, 0, 0}, d1[4] = {0, 0, 0, 0};

    // ---- staging: chunk c into buffer bs (2KB A + 16KB B, linear) ----
    auto stage = [&](int c, int bs) {
        if (tid < 128)
            CP_ASYNC16(sb + bs * SA_BYTES + tid * 16,
                       Ag + ((size_t)(pt * NCHUNK + c) * 128 + tid) * 16);
        #pragma unroll
        for (int it = 0; it < 4; ++it) {
            int idx = it * THREADS + tid;
            CP_ASYNC16(sb + OFF_B + bs * SB_BYTES + idx * 16,
                       Bg + ((size_t)c * 1024 + idx) * 16);
        }
        CP_COMMIT();
    };

    stage(0, 0);
    stage(1, 1);

    for (int c = 0; c < NCHUNK; ++c) {
        const int bs = c & 1;
        if (c < NCHUNK - 1) CP_WAIT1(); else CP_WAIT0();
        __syncthreads();

        const uint32_t sA = sb + bs * SA_BYTES;
        const uint32_t sB = sb + OFF_B + bs * SB_BYTES;
        #pragma unroll
        for (int s = 0; s < 4; ++s) {          // 4 k16-steps per chunk
            uint32_t a0, a1, a2, a3, b0, b1, b2, b3;
            ldsm4(a0, a1, a2, a3, sA + s * 512 + aoff);
            ldsm4(b0, b1, b2, b3, sB + s * 4096 + boff);
            mma16816(d0, a0, a1, a2, a3, b0, b1);   // n-tile wn+0..7
            mma16816(d1, a0, a1, a2, a3, b2, b3);   // n-tile wn+8..15
        }
        __syncthreads();                        // buffer free before restage
        if (c + 2 < NCHUNK) stage(c + 2, bs);
    }

    // ---- epilogue: D frag -> RNE(S/4096), clip, store ----
    // tile row m == ow; block pt -> (b = pt>>4, oh = pt&15)
    const int bq = pt >> 4, oh = pt & 15;
    const int ow0 = lid >> 2, q = lid & 3;
    float* dp[2] = {d0, d1};
    #pragma unroll
    for (int t = 0; t < 2; ++t) {
        #pragma unroll
        for (int e = 0; e < 4; ++e) {
            int n  = wn + t * 8 + q * 2 + (e & 1);
            int ow = ow0 + (e >> 1) * 8;
            float v = rintf(dp[t][e] * (1.0f / 4096.0f));
            v = fminf(fmaxf(v, -32768.0f), 32767.0f);
            out[((bq * COUT + n) * H + oh) * W + ow] = v * (1.0f / 4096.0f);
        }
    }
}

extern "C" void kernel_launch(void* const* d_in, const int* in_sizes, int n_in,
                              void* d_out, int out_size) {
    const float* x = (const float*)d_in[0];
    const float* w = (const float*)d_in[1];
    // defensive: identify tensors by element count (x: 65536, w: 73728)
    if (n_in >= 2 && in_sizes[0] == 73728 && in_sizes[1] == 65536) {
        x = (const float*)d_in[1];
        w = (const float*)d_in[0];
    }
    prep_kernel<<<(P * L + 255) / 256, 256>>>(x, w);
    gemm_kernel<<<64, THREADS>>>((float*)d_out);
}

// round 16
// speedup vs baseline: 1.4060x; 1.4060x over previous
#include <cuda_runtime.h>
#include <cuda_fp16.h>
#include <cstdint>

// HMMA (mma.sync) reformulation of the PUMA crossbar MVM conv (R15 validated:
// rel_err 1.36e-5). Exactness: S = sum_l xi16*dw; fp16-exact split
// xi16 = (xi & ~2047) + (xi & 2047), dw = rint(w*4096) (<2048, exact fp16);
// K folded to 1152. fp32 accumulation rounding ~1 LSB of 1/4096 grid.
//
// R16: latency fixes. Chunk 128 K-elems (NCHUNK 9, was 18) so per-iter MMA
// (~500cyc) covers L2 latency in the double-buffer gap; grid 128 (N split 64)
// so all SMs work; 8 warps with k-step split (s 0-3 vs 4-7) + fp32 partial-D
// combine. SMEM 40KB static.

namespace {
constexpr int CIN = 64, H = 16, W = 16, COUT = 128;
constexpr int L = 576, K2 = 1152, P = 1024;
constexpr int NCHUNK = 9;              // K chunks of 128 elems (16 16B-units)
constexpr int THREADS = 256;
constexpr int SA_BYTES = 4096;         // 16 u x 16 r x 16B
constexpr int SB_BYTES = 16384;        // 16 u x 64 n x 16B
constexpr int OFF_B = 2 * SA_BYTES;    // [A0][A1][B0][B1] = 40960 B
}

__device__ __align__(16) __half A_g[P * K2];     // [pt][c][u][r][8h]
__device__ __align__(16) __half B_g[COUT * K2];  // [c][u][n][8h]

__device__ __forceinline__ uint32_t smem_u32(const void* p) {
    uint32_t a;
    asm("{ .reg .u64 t; cvta.to.shared.u64 t, %1; cvt.u32.u64 %0, t; }"
        : "=r"(a) : "l"(p));
    return a;
}
#define CP_ASYNC16(dst, src) \
    asm volatile("cp.async.cg.shared.global [%0], [%1], 16;" \
                 :: "r"(dst), "l"(src) : "memory")
#define CP_COMMIT() asm volatile("cp.async.commit_group;" ::: "memory")
#define CP_WAIT1()  asm volatile("cp.async.wait_group 1;" ::: "memory")
#define CP_WAIT0()  asm volatile("cp.async.wait_group 0;" ::: "memory")

__device__ __forceinline__ void ldsm4(uint32_t& r0, uint32_t& r1,
                                      uint32_t& r2, uint32_t& r3, uint32_t a) {
    asm volatile("ldmatrix.sync.aligned.m8n8.x4.shared.b16 {%0,%1,%2,%3}, [%4];"
                 : "=r"(r0), "=r"(r1), "=r"(r2), "=r"(r3) : "r"(a));
}
__device__ __forceinline__ void mma16816(float* d, uint32_t a0, uint32_t a1,
                                         uint32_t a2, uint32_t a3,
                                         uint32_t b0, uint32_t b1) {
    asm volatile(
        "mma.sync.aligned.m16n8k16.row.col.f32.f16.f16.f32 "
        "{%0,%1,%2,%3}, {%4,%5,%6,%7}, {%8,%9}, {%0,%1,%2,%3};"
        : "+f"(d[0]), "+f"(d[1]), "+f"(d[2]), "+f"(d[3])
        : "r"(a0), "r"(a1), "r"(a2), "r"(a3), "r"(b0), "r"(b1));
}

// ---- prep: quantize, fp16-split, im2col into the staging layouts ----
__global__ void prep_kernel(const float* __restrict__ x,
                            const float* __restrict__ w)
{
    int i = blockIdx.x * blockDim.x + threadIdx.x;
    if (i < COUT * L) {
        int n = i / L, l = i - n * L;
        __half h = __float2half_rn(rintf(w[i] * 4096.0f));   // |dw|<2048 exact
        #pragma unroll
        for (int d = 0; d < 2; ++d) {
            int k = l + d * L;
            int c = k >> 7, u = (k >> 3) & 15, hh = k & 7;
            B_g[((c * 16 + u) * COUT + n) * 8 + hh] = h;
        }
    }
    if (i < P * L) {
        int p = i / L, l = i - p * L;
        int b = p >> 8, oh = (p >> 4) & 15, ow = p & 15;
        int ci = l / 9, r9 = l - ci * 9, ki = r9 / 3, kj = r9 - ki * 3;
        int row = oh - 1 + ki, col = ow - 1 + kj;
        int xi = 0;
        if ((unsigned)row < 16u && (unsigned)col < 16u)
            xi = (int)rintf(x[((b * CIN + ci) * H + row) * W + col] * 4096.0f);
        xi = (xi << 16) >> 16;                     // 16-bit two's complement
        int hi = xi & ~2047, lo = xi & 2047;       // exact fp16 split
        int pt = p >> 4, r = p & 15;
        int vals[2] = {hi, lo};
        #pragma unroll
        for (int d = 0; d < 2; ++d) {
            int k = l + d * L;
            int c = k >> 7, u = (k >> 3) & 15, hh = k & 7;
            A_g[(((pt * NCHUNK + c) * 16 + u) * 16 + r) * 8 + hh] =
                __float2half_rn((float)vals[d]);
        }
    }
}

// ---- GEMM: 128 blocks = 64 P-tiles x 2 N-halves; 8 warps, k-step split ----
__global__ __launch_bounds__(THREADS, 1)
void gemm_kernel(float* __restrict__ out)
{
    __shared__ __align__(16) char smem[OFF_B + 2 * SB_BYTES];   // 40960 B
    const uint32_t sb = smem_u32(smem);
    const int tid = threadIdx.x, wid = tid >> 5, lid = tid & 31;
    const int pt = blockIdx.x >> 1, nh = blockIdx.x & 1;
    const int sgrp = wid >> 2;            // k-step half: s = sgrp*4 + ss
    const int wn = (wid & 3) * 16;        // n-tile within the 64-wide half

    const char* Ag = (const char*)A_g;
    const char* Bg = (const char*)B_g;

    // lane offsets for ldmatrix fragments
    const uint32_t aoff = (uint32_t)((lid >> 4) * 256
                        + (((lid >> 3) & 1) * 8 + (lid & 7)) * 16);
    const uint32_t boff = (uint32_t)(((lid >> 3) & 1) * 1024
                        + (wn + ((lid >> 4) * 8) + (lid & 7)) * 16);

    float d0[4] = {0, 0, 0, 0}, d1[4] = {0, 0, 0, 0};

    auto stage = [&](int c, int bs) {
        // A chunk: 256 x 16B, linear
        CP_ASYNC16(sb + bs * SA_BYTES + tid * 16,
                   Ag + ((size_t)(pt * NCHUNK + c) * 256 + tid) * 16);
        // B chunk-half: 1024 x 16B, [u(16)][n(64)]
        #pragma unroll
        for (int it = 0; it < 4; ++it) {
            int idx = it * THREADS + tid;
            int u = idx >> 6, r = idx & 63;
            CP_ASYNC16(sb + OFF_B + bs * SB_BYTES + idx * 16,
                       Bg + ((size_t)(c * 16 + u) * COUT + nh * 64 + r) * 16);
        }
        CP_COMMIT();
    };

    stage(0, 0);
    stage(1, 1);

    for (int c = 0; c < NCHUNK; ++c) {
        const int bs = c & 1;
        if (c < NCHUNK - 1) CP_WAIT1(); else CP_WAIT0();
        __syncthreads();

        const uint32_t sA = sb + bs * SA_BYTES;
        const uint32_t sB = sb + OFF_B + bs * SB_BYTES;
        #pragma unroll
        for (int ss = 0; ss < 4; ++ss) {          // this warp-group's k16 steps
            const int s = sgrp * 4 + ss;
            uint32_t a0, a1, a2, a3, b0, b1, b2, b3;
            ldsm4(a0, a1, a2, a3, sA + s * 512 + aoff);
            ldsm4(b0, b1, b2, b3, sB + s * 2048 + boff);
            mma16816(d0, a0, a1, a2, a3, b0, b1);   // n wn+0..7
            mma16816(d1, a0, a1, a2, a3, b2, b3);   // n wn+8..15
        }
        __syncthreads();                        // buffer free before restage
        if (c + 2 < NCHUNK) stage(c + 2, bs);
    }

    // ---- combine k-split partials (sgrp 1 -> sgrp 0) via SMEM ----
    __syncthreads();                            // staging buffers now reusable
    float* red = (float*)smem;                  // 4 warps x 32 lanes x 8 floats
    if (sgrp == 1) {
        float* dst = red + ((wid & 3) * 32 + lid) * 8;
        #pragma unroll
        for (int e = 0; e < 4; ++e) { dst[e] = d0[e]; dst[4 + e] = d1[e]; }
    }
    __syncthreads();
    if (sgrp == 1) return;
    {
        const float* src = red + ((wid & 3) * 32 + lid) * 8;
        #pragma unroll
        for (int e = 0; e < 4; ++e) { d0[e] += src[e]; d1[e] += src[4 + e]; }
    }

    // ---- epilogue: RNE(S/4096), clip, store. tile row m == ow ----
    const int bq = pt >> 4, oh = pt & 15;
    const int ow0 = lid >> 2, q = lid & 3;
    float* dp[2] = {d0, d1};
    #pragma unroll
    for (int t = 0; t < 2; ++t) {
        #pragma unroll
        for (int e = 0; e < 4; ++e) {
            int n  = nh * 64 + wn + t * 8 + q * 2 + (e & 1);
            int ow = ow0 + (e >> 1) * 8;
            float v = rintf(dp[t][e] * (1.0f / 4096.0f));
            v = fminf(fmaxf(v, -32768.0f), 32767.0f);
            out[((bq * COUT + n) * H + oh) * W + ow] = v * (1.0f / 4096.0f);
        }
    }
}

extern "C" void kernel_launch(void* const* d_in, const int* in_sizes, int n_in,
                              void* d_out, int out_size) {
    const float* x = (const float*)d_in[0];
    const float* w = (const float*)d_in[1];
    // defensive: identify tensors by element count (x: 65536, w: 73728)
    if (n_in >= 2 && in_sizes[0] == 73728 && in_sizes[1] == 65536) {
        x = (const float*)d_in[1];
        w = (const float*)d_in[0];
    }
    prep_kernel<<<(P * L + 255) / 256, 256>>>(x, w);
    gemm_kernel<<<128, THREADS>>>((float*)d_out);
}